// round 15
// baseline (speedup 1.0000x reference)
#include <cuda_runtime.h>
#include <cuda_bf16.h>
#include <cuda_fp16.h>

// RWSE encoder: diag(P^k) for k=1..16, then linear [16 -> 8].
// P = D^{-1} A, sparse (E=65536 edges over N=4096 nodes).
//
//   C_p := (P^T)^p stored fp16 for p = 2..8 (g_Ch[p-2], 32 MB each).
//   C_2 by flat 2-hop sparse scatter; C_3..C_8 by 6 gather-SpMM steps
//   (fp16 in, packed f32x2 FMA accum).  diag(P^p) extracted from fp32
//   accums BEFORE quantization (p=2 from the smem row).  k=1 = self-loop
//   count / deg.  k=9..16 in one pairing kernel (16384-block tile grid):
//   diag(P^{a+b})[i] = sum_t C_a[t,i]*C_b[i,t], (a,b)=(4,5),(5,5),(3,8)..(8,8).
//   out = diag @ w^T + b.

#define NN 4096
#define EE 65536
#define NSLOT 128
#define WL 16
#define OD 8

// ---- static device scratch (no allocations allowed) ----
__device__ __half g_Ch[7][(size_t)NN * NN];  // 224 MB: C_2..C_8 (p -> g_Ch[p-2])
__device__ int    g_is64;
__device__ int    g_degout[NN];
__device__ float  g_vdeg[NN];                // 1/max(degout,1)
__device__ int    g_cnt[NN];                 // in-edge counts (by dest)
__device__ int    g_src[NN * NSLOT];         // in-edge src lists
__device__ float  g_diag[WL * NN];           // diag[k-1][i], fp32

// Packed f32x2 helpers (Blackwell; FFMA2 reachable only via PTX).
__device__ __forceinline__ unsigned long long pack_f32x2(float lo, float hi) {
    unsigned long long r;
    asm("mov.b64 %0, {%1, %2};" : "=l"(r) : "f"(lo), "f"(hi));
    return r;
}
__device__ __forceinline__ void fma_f32x2(unsigned long long& acc,
                                          unsigned long long a,
                                          unsigned long long b) {
    asm("fma.rn.f32x2 %0, %1, %2, %0;" : "+l"(acc) : "l"(a), "l"(b));
}
__device__ __forceinline__ float2 unpack_f32x2(unsigned long long v) {
    float lo, hi;
    asm("mov.b64 {%0, %1}, %2;" : "=f"(lo), "=f"(hi) : "l"(v));
    return make_float2(lo, hi);
}

// Zero counters + all of diag; block 0 warp 0 detects edge dtype:
// int64 little-endian values in [0,4096) have all-zero odd 32-bit words.
__global__ void k_init(const int* __restrict__ raw) {
    int i = blockIdx.x * blockDim.x + threadIdx.x;
    if (i < WL * NN) g_diag[i] = 0.0f;
    if (i < NN) { g_cnt[i] = 0; g_degout[i] = 0; }
    if (blockIdx.x == 0 && threadIdx.x < 32) {
        int v = raw[2 * threadIdx.x + 1];
        unsigned nz = __ballot_sync(0xffffffffu, v != 0);
        if (threadIdx.x == 0) g_is64 = (nz == 0) ? 1 : 0;
    }
}

// Degree counting + in-edge list + self-loop count, reading raw edges.
__global__ void k_scatter(const int* __restrict__ raw, int E) {
    int e = blockIdx.x * blockDim.x + threadIdx.x;
    if (e >= E) return;
    int r, c;
    if (g_is64) {
        r = (int)(((const long long*)raw)[e]);
        c = (int)(((const long long*)raw)[E + e]);
    } else {
        r = raw[e];
        c = raw[E + e];
    }
    if (r < 0 || r >= NN || c < 0 || c >= NN) return;
    atomicAdd(&g_degout[r], 1);
    int p = atomicAdd(&g_cnt[c], 1);
    if (p < NSLOT) g_src[c * NSLOT + p] = r;
    if (r == c) atomicAdd(&g_diag[r], 1.0f);         // self-loop multiplicity
}

// vdeg + finalize diag(P^1) = selfloops * 1/deg.
__global__ void k_prep() {
    int i = blockIdx.x * blockDim.x + threadIdx.x;
    if (i >= NN) return;
    int d = g_degout[i]; if (d < 1) d = 1;
    float v = 1.0f / (float)d;
    g_vdeg[i] = v;
    g_diag[i] *= v;
}

// C_2[c][m] = sum_{(r->c)} v_r * sum_{(m->r)} v_m.  512 threads: warp w
// covers hop-1 edge w (16 warps ~ deg), lanes spread over hop-2 edges.
// diag(P^2) taken from the fp32 smem row pre-quantization.
__global__ void __launch_bounds__(512) k_build_c2() {
    __shared__ float srow[NN];
    int c = blockIdx.x, t = threadIdx.x;
    int w = t >> 5, lane = t & 31;
    float4* sz = (float4*)srow;
    for (int q = t; q < NN / 4; q += 512) sz[q] = make_float4(0.f, 0.f, 0.f, 0.f);
    __syncthreads();

    int n1 = g_cnt[c]; if (n1 > NSLOT) n1 = NSLOT;
    for (int e1 = w; e1 < n1; e1 += 16) {
        int r1 = g_src[c * NSLOT + e1];
        float v1 = g_vdeg[r1];
        int n2 = g_cnt[r1]; if (n2 > NSLOT) n2 = NSLOT;
        for (int e2 = lane; e2 < n2; e2 += 32) {
            int r2 = g_src[r1 * NSLOT + e2];
            atomicAdd(&srow[r2], v1 * g_vdeg[r2]);
        }
    }
    __syncthreads();

    if (t == 0) g_diag[NN + c] = srow[c];            // diag(P^2)
    uint4* o = (uint4*)(g_Ch[0] + (size_t)c * NN);
    const float4* s4 = (const float4*)srow;
    for (int q = t; q < NN / 8; q += 512) {
        float4 f0 = s4[2 * q], f1 = s4[2 * q + 1];
        __half2 hh[4];
        hh[0] = __floats2half2_rn(f0.x, f0.y);
        hh[1] = __floats2half2_rn(f0.z, f0.w);
        hh[2] = __floats2half2_rn(f1.x, f1.y);
        hh[3] = __floats2half2_rn(f1.z, f1.w);
        o[q] = *(uint4*)hh;
    }
}

// SpMM: C_p[c][:] = sum_{(r->c)} v * C_{p-1}[r][:].
// 512 threads; thread t owns cols [8t, 8t+8) => one uint4 (8 fp16) per edge.
// fp16 gather, packed f32x2 FMA into fp32 accumulators.
__global__ void __launch_bounds__(512) k_spmm(int p) {
    const __half* __restrict__ in = g_Ch[p - 3];
    int c = blockIdx.x;
    int t = threadIdx.x;

    __shared__ int   s_src[NSLOT];
    __shared__ float s_val[NSLOT];
    int n = g_cnt[c]; if (n > NSLOT) n = NSLOT;
    if (t < n) {
        int r = g_src[c * NSLOT + t];
        s_src[t] = r;
        s_val[t] = g_vdeg[r];
    }
    __syncthreads();

    unsigned long long acc[4];
#pragma unroll
    for (int q = 0; q < 4; q++) acc[q] = pack_f32x2(0.f, 0.f);

#pragma unroll 2
    for (int e = 0; e < n; e++) {
        const uint4* row = (const uint4*)(in + (size_t)s_src[e] * NN);
        float v = s_val[e];
        unsigned long long vv = pack_f32x2(v, v);
        uint4 u = __ldg(row + t);
        const __half2* h = (const __half2*)&u;
#pragma unroll
        for (int q = 0; q < 4; q++) {
            float2 f = __half22float2(h[q]);
            fma_f32x2(acc[q], pack_f32x2(f.x, f.y), vv);
        }
    }

    float2 a0 = unpack_f32x2(acc[0]);
    float2 a1 = unpack_f32x2(acc[1]);
    float2 a2 = unpack_f32x2(acc[2]);
    float2 a3 = unpack_f32x2(acc[3]);

    int base = 8 * t;
    if (c >= base && c < base + 8) {
        float vals[8] = {a0.x, a0.y, a1.x, a1.y, a2.x, a2.y, a3.x, a3.y};
        g_diag[(p - 1) * NN + c] = vals[c - base];
    }

    __half2 hh[4];
    hh[0] = __floats2half2_rn(a0.x, a0.y);
    hh[1] = __floats2half2_rn(a1.x, a1.y);
    hh[2] = __floats2half2_rn(a2.x, a2.y);
    hh[3] = __floats2half2_rn(a3.x, a3.y);
    ((uint4*)(g_Ch[p - 2] + (size_t)c * NN))[t] = *(uint4*)hh;
}

// All of k=9..16: diag(P^{a+b})[i] = sum_t C_a[t,i] * C_b[i,t].
// (a,b) per warp ty (k=9+ty): (4,5),(5,5),(3,8),(4,8),(5,8),(6,8),(7,8),(8,8).
// Full 2D tile grid (16384 blocks) for occupancy; spread gmem atomics.
__global__ void __launch_bounds__(256) k_pair() {
    int i0 = blockIdx.x * 32;
    int t0 = blockIdx.y * 32;
    int tx = threadIdx.x;   // 0..31
    int ty = threadIdx.y;   // 0..7 (= warp id)

    __shared__ float B5[32][33];
    __shared__ float B8[32][33];
#pragma unroll
    for (int q = 0; q < 4; q++) {
        int r = ty + 8 * q;
        B5[r][tx] = __half2float(g_Ch[3][(size_t)(i0 + r) * NN + t0 + tx]);
        B8[r][tx] = __half2float(g_Ch[6][(size_t)(i0 + r) * NN + t0 + tx]);
    }
    __syncthreads();

    float part[8];
#pragma unroll
    for (int j = 0; j < 8; j++) part[j] = 0.f;

#pragma unroll
    for (int q = 0; q < 4; q++) {
        int tt = ty + 8 * q;
        size_t off = (size_t)(t0 + tt) * NN + i0 + tx;
        float a3 = __half2float(g_Ch[1][off]);
        float a4 = __half2float(g_Ch[2][off]);
        float a5 = __half2float(g_Ch[3][off]);
        float a6 = __half2float(g_Ch[4][off]);
        float a7 = __half2float(g_Ch[5][off]);
        float a8 = __half2float(g_Ch[6][off]);
        float b5 = B5[tx][tt];
        float b8 = B8[tx][tt];
        part[0] += a4 * b5;      // k =  9 = 4+5
        part[1] += a5 * b5;      // k = 10 = 5+5
        part[2] += a3 * b8;      // k = 11 = 3+8
        part[3] += a4 * b8;      // k = 12 = 4+8
        part[4] += a5 * b8;      // k = 13 = 5+8
        part[5] += a6 * b8;      // k = 14 = 6+8
        part[6] += a7 * b8;      // k = 15 = 7+8
        part[7] += a8 * b8;      // k = 16 = 8+8
    }

    __shared__ float red[8][8][33];
#pragma unroll
    for (int j = 0; j < 8; j++) red[j][ty][tx] = part[j];
    __syncthreads();

    {
        float s = red[ty][0][tx] + red[ty][1][tx] + red[ty][2][tx] + red[ty][3][tx]
                + red[ty][4][tx] + red[ty][5][tx] + red[ty][6][tx] + red[ty][7][tx];
        atomicAdd(&g_diag[(8 + ty) * NN + i0 + tx], s);
    }
}

// out[i][d] = b[d] + sum_k diag_k[i] * w[d][k]
__global__ void k_linear(const float* __restrict__ w, const float* __restrict__ b,
                         float* __restrict__ out) {
    int i = blockIdx.x * blockDim.x + threadIdx.x;
    if (i >= NN) return;
    float dv[WL];
#pragma unroll
    for (int k = 0; k < WL; k++) dv[k] = g_diag[k * NN + i];
#pragma unroll
    for (int d = 0; d < OD; d++) {
        float s = b[d];
#pragma unroll
        for (int k = 0; k < WL; k++) s += dv[k] * w[d * WL + k];
        out[i * OD + d] = s;
    }
}

extern "C" void kernel_launch(void* const* d_in, const int* in_sizes, int n_in,
                              void* d_out, int out_size) {
    const int* ei_raw = (const int*)d_in[0];           // edge_index [2, E]
    int E = in_sizes[0] / 2;
    if (E > EE) E = EE;

    const float* w = nullptr;
    const float* b = nullptr;
    for (int i = 1; i < n_in; i++) {
        if (in_sizes[i] == OD * WL)      w = (const float*)d_in[i];
        else if (in_sizes[i] == OD)      b = (const float*)d_in[i];
    }
    if (!w) w = (const float*)d_in[n_in - 2];
    if (!b) b = (const float*)d_in[n_in - 1];

    float* out = (float*)d_out;                        // [N, 8] fp32

    k_init<<<(WL * NN) / 256, 256>>>(ei_raw);
    k_scatter<<<(E + 255) / 256, 256>>>(ei_raw, E);
    k_prep<<<NN / 256, 256>>>();
    k_build_c2<<<NN, 512>>>();
    for (int p = 3; p <= 8; p++)
        k_spmm<<<NN, 512>>>(p);
    dim3 bb(32, 8), gg(NN / 32, NN / 32);
    k_pair<<<gg, bb>>>();
    k_linear<<<NN / 256, 256>>>(w, b, out);
}

// round 17
// speedup vs baseline: 1.1373x; 1.1373x over previous
#include <cuda_runtime.h>
#include <cuda_bf16.h>
#include <cuda_fp16.h>

// RWSE encoder: diag(P^k) for k=1..16, then linear [16 -> 8].
// P = D^{-1} A, sparse (E=65536 edges over N=4096 nodes).
//
//   C_p := (P^T)^p stored fp16 for p = 2..8 (g_Ch[p-2], 32 MB each).
//   C_2 by flat 2-hop sparse scatter; C_3..C_8 by 6 gather-SpMM steps
//   (fp16 in, fp32 accum) -- at the LTS bandwidth floor (~38.8 us/step).
//   diag(P^p) extracted from fp32 accums BEFORE quantization.
//   k=1 = self-loop count / deg.  k=9..16 in one pairing kernel
//   (64-wide i-tiles, half2 A-loads): diag(P^{a+b})[i] =
//   sum_t C_a[t,i]*C_b[i,t], (a,b)=(4,5),(5,5),(3,8)..(8,8).
//   out = diag @ w^T + b.

#define NN 4096
#define EE 65536
#define NSLOT 128
#define WL 16
#define OD 8

// ---- static device scratch (no allocations allowed) ----
__device__ __half g_Ch[7][(size_t)NN * NN];  // 224 MB: C_2..C_8 (p -> g_Ch[p-2])
__device__ int    g_is64;
__device__ int    g_degout[NN];
__device__ float  g_vdeg[NN];                // 1/max(degout,1)
__device__ int    g_cnt[NN];                 // in-edge counts (by dest)
__device__ int    g_src[NN * NSLOT];         // in-edge src lists
__device__ float  g_diag[WL * NN];           // diag[k-1][i], fp32

// Zero counters + all of diag; block 0 warp 0 detects edge dtype:
// int64 little-endian values in [0,4096) have all-zero odd 32-bit words.
__global__ void k_init(const int* __restrict__ raw) {
    int i = blockIdx.x * blockDim.x + threadIdx.x;
    if (i < WL * NN) g_diag[i] = 0.0f;
    if (i < NN) { g_cnt[i] = 0; g_degout[i] = 0; }
    if (blockIdx.x == 0 && threadIdx.x < 32) {
        int v = raw[2 * threadIdx.x + 1];
        unsigned nz = __ballot_sync(0xffffffffu, v != 0);
        if (threadIdx.x == 0) g_is64 = (nz == 0) ? 1 : 0;
    }
}

// Degree counting + in-edge list + self-loop count, reading raw edges.
__global__ void k_scatter(const int* __restrict__ raw, int E) {
    int e = blockIdx.x * blockDim.x + threadIdx.x;
    if (e >= E) return;
    int r, c;
    if (g_is64) {
        r = (int)(((const long long*)raw)[e]);
        c = (int)(((const long long*)raw)[E + e]);
    } else {
        r = raw[e];
        c = raw[E + e];
    }
    if (r < 0 || r >= NN || c < 0 || c >= NN) return;
    atomicAdd(&g_degout[r], 1);
    int p = atomicAdd(&g_cnt[c], 1);
    if (p < NSLOT) g_src[c * NSLOT + p] = r;
    if (r == c) atomicAdd(&g_diag[r], 1.0f);         // self-loop multiplicity
}

// vdeg + finalize diag(P^1) = selfloops * 1/deg.
__global__ void k_prep() {
    int i = blockIdx.x * blockDim.x + threadIdx.x;
    if (i >= NN) return;
    int d = g_degout[i]; if (d < 1) d = 1;
    float v = 1.0f / (float)d;
    g_vdeg[i] = v;
    g_diag[i] *= v;
}

// C_2[c][m] = sum_{(r->c)} v_r * sum_{(m->r)} v_m.  256 threads: warp w
// covers hop-1 edges {w, w+8, ...}, lanes spread over hop-2 edges.
// diag(P^2) taken from the fp32 smem row pre-quantization.
__global__ void __launch_bounds__(256) k_build_c2() {
    __shared__ float srow[NN];
    int c = blockIdx.x, t = threadIdx.x;
    int w = t >> 5, lane = t & 31;
    float4* sz = (float4*)srow;
    for (int q = t; q < NN / 4; q += 256) sz[q] = make_float4(0.f, 0.f, 0.f, 0.f);
    __syncthreads();

    int n1 = g_cnt[c]; if (n1 > NSLOT) n1 = NSLOT;
    for (int e1 = w; e1 < n1; e1 += 8) {
        int r1 = g_src[c * NSLOT + e1];
        float v1 = g_vdeg[r1];
        int n2 = g_cnt[r1]; if (n2 > NSLOT) n2 = NSLOT;
        for (int e2 = lane; e2 < n2; e2 += 32) {
            int r2 = g_src[r1 * NSLOT + e2];
            atomicAdd(&srow[r2], v1 * g_vdeg[r2]);
        }
    }
    __syncthreads();

    if (t == 0) g_diag[NN + c] = srow[c];            // diag(P^2)
    uint4* o = (uint4*)(g_Ch[0] + (size_t)c * NN);
    const float4* s4 = (const float4*)srow;
    for (int q = t; q < NN / 8; q += 256) {
        float4 f0 = s4[2 * q], f1 = s4[2 * q + 1];
        __half2 hh[4];
        hh[0] = __floats2half2_rn(f0.x, f0.y);
        hh[1] = __floats2half2_rn(f0.z, f0.w);
        hh[2] = __floats2half2_rn(f1.x, f1.y);
        hh[3] = __floats2half2_rn(f1.z, f1.w);
        o[q] = *(uint4*)hh;
    }
}

// SpMM: C_p[c][:] = sum_{(r->c)} v * C_{p-1}[r][:].  fp16 gather, fp32 accum.
// Thread t owns columns [8t,8t+8) and [2048+8t, 2048+8t+8).  (R14-exact.)
__global__ void __launch_bounds__(256) k_spmm(int p) {
    const __half* __restrict__ in = g_Ch[p - 3];
    int c = blockIdx.x;
    int t = threadIdx.x;

    __shared__ int   s_src[NSLOT];
    __shared__ float s_val[NSLOT];
    int n = g_cnt[c]; if (n > NSLOT) n = NSLOT;
    if (t < n) {
        int r = g_src[c * NSLOT + t];
        s_src[t] = r;
        s_val[t] = g_vdeg[r];
    }
    __syncthreads();

    float acc[16];
#pragma unroll
    for (int s = 0; s < 16; s++) acc[s] = 0.0f;

#pragma unroll 2
    for (int e = 0; e < n; e++) {
        const uint4* row = (const uint4*)(in + (size_t)s_src[e] * NN);
        float v = s_val[e];
        uint4 u0 = __ldg(row + t);
        uint4 u1 = __ldg(row + t + 256);
        const __half2* h0 = (const __half2*)&u0;
        const __half2* h1 = (const __half2*)&u1;
#pragma unroll
        for (int q = 0; q < 4; q++) {
            float2 f0 = __half22float2(h0[q]);
            float2 f1 = __half22float2(h1[q]);
            acc[2 * q]         += v * f0.x;
            acc[2 * q + 1]     += v * f0.y;
            acc[8 + 2 * q]     += v * f1.x;
            acc[8 + 2 * q + 1] += v * f1.y;
        }
    }

    int base0 = 8 * t, base1 = 2048 + 8 * t;
    if (c >= base0 && c < base0 + 8)
        g_diag[(p - 1) * NN + c] = acc[c - base0];
    if (c >= base1 && c < base1 + 8)
        g_diag[(p - 1) * NN + c] = acc[8 + (c - base1)];

    __half2 hh[8];
#pragma unroll
    for (int q = 0; q < 4; q++) {
        hh[q]     = __floats2half2_rn(acc[2 * q],     acc[2 * q + 1]);
        hh[4 + q] = __floats2half2_rn(acc[8 + 2 * q], acc[8 + 2 * q + 1]);
    }
    uint4* o = (uint4*)(g_Ch[p - 2] + (size_t)c * NN);
    o[t]       = *(uint4*)&hh[0];
    o[t + 256] = *(uint4*)&hh[4];
}

// All of k=9..16: diag(P^{a+b})[i] = sum_t C_a[t,i] * C_b[i,t].
// (a,b) per warp ty (k=9+ty): (4,5),(5,5),(3,8),(4,8),(5,8),(6,8),(7,8),(8,8).
// 64-wide i-tiles: each thread covers i = i0+2tx, i0+2tx+1 via half2 loads.
// Grid 64 x 128 = 8192 blocks; per-block partials via spread gmem atomics.
__global__ void __launch_bounds__(256) k_pair() {
    int i0 = blockIdx.x * 64;
    int t0 = blockIdx.y * 32;
    int tx = threadIdx.x;   // 0..31
    int ty = threadIdx.y;   // 0..7 (= warp id)

    __shared__ float B5[64][33];
    __shared__ float B8[64][33];
#pragma unroll
    for (int q = 0; q < 8; q++) {
        int r = ty + 8 * q;
        B5[r][tx] = __half2float(g_Ch[3][(size_t)(i0 + r) * NN + t0 + tx]);
        B8[r][tx] = __half2float(g_Ch[6][(size_t)(i0 + r) * NN + t0 + tx]);
    }
    __syncthreads();

    float2 part[8];
#pragma unroll
    for (int j = 0; j < 8; j++) part[j] = make_float2(0.f, 0.f);

    int iA = i0 + 2 * tx;
#pragma unroll
    for (int q = 0; q < 4; q++) {
        int tt = ty + 8 * q;
        size_t off2 = ((size_t)(t0 + tt) * NN + iA) >> 1;   // half2 index
        float2 a3 = __half22float2(((const __half2*)g_Ch[1])[off2]);
        float2 a4 = __half22float2(((const __half2*)g_Ch[2])[off2]);
        float2 a5 = __half22float2(((const __half2*)g_Ch[3])[off2]);
        float2 a6 = __half22float2(((const __half2*)g_Ch[4])[off2]);
        float2 a7 = __half22float2(((const __half2*)g_Ch[5])[off2]);
        float2 a8 = __half22float2(((const __half2*)g_Ch[6])[off2]);
        float b5x = B5[2 * tx][tt],     b8x = B8[2 * tx][tt];
        float b5y = B5[2 * tx + 1][tt], b8y = B8[2 * tx + 1][tt];
        part[0].x += a4.x * b5x;  part[0].y += a4.y * b5y;   // k =  9 = 4+5
        part[1].x += a5.x * b5x;  part[1].y += a5.y * b5y;   // k = 10 = 5+5
        part[2].x += a3.x * b8x;  part[2].y += a3.y * b8y;   // k = 11 = 3+8
        part[3].x += a4.x * b8x;  part[3].y += a4.y * b8y;   // k = 12 = 4+8
        part[4].x += a5.x * b8x;  part[4].y += a5.y * b8y;   // k = 13 = 5+8
        part[5].x += a6.x * b8x;  part[5].y += a6.y * b8y;   // k = 14 = 6+8
        part[6].x += a7.x * b8x;  part[6].y += a7.y * b8y;   // k = 15 = 7+8
        part[7].x += a8.x * b8x;  part[7].y += a8.y * b8y;   // k = 16 = 8+8
    }
    __syncthreads();                                         // B tiles dead

    __shared__ float2 red[8][8][33];
#pragma unroll
    for (int j = 0; j < 8; j++) red[j][ty][tx] = part[j];
    __syncthreads();

    {
        float2 s = make_float2(0.f, 0.f);
#pragma unroll
        for (int wq = 0; wq < 8; wq++) {
            float2 v = red[ty][wq][tx];
            s.x += v.x; s.y += v.y;
        }
        atomicAdd(&g_diag[(8 + ty) * NN + iA],     s.x);
        atomicAdd(&g_diag[(8 + ty) * NN + iA + 1], s.y);
    }
}

// out[i][d] = b[d] + sum_k diag_k[i] * w[d][k]
__global__ void k_linear(const float* __restrict__ w, const float* __restrict__ b,
                         float* __restrict__ out) {
    int i = blockIdx.x * blockDim.x + threadIdx.x;
    if (i >= NN) return;
    float dv[WL];
#pragma unroll
    for (int k = 0; k < WL; k++) dv[k] = g_diag[k * NN + i];
#pragma unroll
    for (int d = 0; d < OD; d++) {
        float s = b[d];
#pragma unroll
        for (int k = 0; k < WL; k++) s += dv[k] * w[d * WL + k];
        out[i * OD + d] = s;
    }
}

extern "C" void kernel_launch(void* const* d_in, const int* in_sizes, int n_in,
                              void* d_out, int out_size) {
    const int* ei_raw = (const int*)d_in[0];           // edge_index [2, E]
    int E = in_sizes[0] / 2;
    if (E > EE) E = EE;

    const float* w = nullptr;
    const float* b = nullptr;
    for (int i = 1; i < n_in; i++) {
        if (in_sizes[i] == OD * WL)      w = (const float*)d_in[i];
        else if (in_sizes[i] == OD)      b = (const float*)d_in[i];
    }
    if (!w) w = (const float*)d_in[n_in - 2];
    if (!b) b = (const float*)d_in[n_in - 1];

    float* out = (float*)d_out;                        // [N, 8] fp32

    k_init<<<(WL * NN) / 256, 256>>>(ei_raw);
    k_scatter<<<(E + 255) / 256, 256>>>(ei_raw, E);
    k_prep<<<NN / 256, 256>>>();
    k_build_c2<<<NN, 256>>>();
    for (int p = 3; p <= 8; p++)
        k_spmm<<<NN, 256>>>(p);
    dim3 bb(32, 8), gg(NN / 64, NN / 32);
    k_pair<<<gg, bb>>>();
    k_linear<<<NN / 256, 256>>>(w, b, out);
}